// round 1
// baseline (speedup 1.0000x reference)
#include <cuda_runtime.h>
#include <cuda_bf16.h>
#include <mma.h>
#include <math.h>

using namespace nvcuda;

#define NTOK 4096
#define DDIM 1024
#define HDIM 4096
#define ODIM 1024
#define NEXP 8
#define NPAIR 8192

#define BM 128
#define BN 128
#define BK 32
#define ALD 40
#define BLD 136
#define CLD 132

// gemm smem: A(hi+lo) 2 bufs + B(hi+lo) 2 bufs, C-tile aliased on top
#define SMEM_GEMM (2*2*BM*ALD*2 + 2*2*BK*BLD*2)   // 75776 bytes
#define SMEM_ROUTER (16*DDIM*4)                    // 65536 bytes

// ---------------- scratch (device globals; no allocation) ----------------
__device__ int   g_cnt[NEXP];
__device__ int   g_off[NEXP];
__device__ int   g_tok[NEXP*NTOK];
__device__ float g_gate[NEXP*NTOK];
__device__ __nv_bfloat16 g_xhi[NTOK*DDIM];
__device__ __nv_bfloat16 g_xlo[NTOK*DDIM];
__device__ __nv_bfloat16 g_w1hi[NEXP*DDIM*HDIM];
__device__ __nv_bfloat16 g_w1lo[NEXP*DDIM*HDIM];
__device__ __nv_bfloat16 g_w2hi[NEXP*HDIM*ODIM];
__device__ __nv_bfloat16 g_w2lo[NEXP*HDIM*ODIM];
__device__ __nv_bfloat16 g_hhi[(size_t)NPAIR*HDIM];
__device__ __nv_bfloat16 g_hlo[(size_t)NPAIR*HDIM];

// ---------------- fp32 -> bf16 hi/lo split ----------------
__global__ void split_kernel(const float4* __restrict__ src,
                             __nv_bfloat162* __restrict__ hi,
                             __nv_bfloat162* __restrict__ lo, int n4) {
    int i = blockIdx.x * blockDim.x + threadIdx.x;
    if (i >= n4) return;
    float4 v = src[i];
    __nv_bfloat16 h0 = __float2bfloat16(v.x);
    __nv_bfloat16 h1 = __float2bfloat16(v.y);
    __nv_bfloat16 h2 = __float2bfloat16(v.z);
    __nv_bfloat16 h3 = __float2bfloat16(v.w);
    hi[2*i]   = __halves2bfloat162(h0, h1);
    hi[2*i+1] = __halves2bfloat162(h2, h3);
    lo[2*i]   = __halves2bfloat162(__float2bfloat16(v.x - __bfloat162float(h0)),
                                   __float2bfloat16(v.y - __bfloat162float(h1)));
    lo[2*i+1] = __halves2bfloat162(__float2bfloat16(v.z - __bfloat162float(h2)),
                                   __float2bfloat16(v.w - __bfloat162float(h3)));
}

// ---------------- router: noisy top-2 gating + expert lists ----------------
__global__ void router_kernel(const float* __restrict__ x,
                              const float* __restrict__ noise,
                              const float* __restrict__ Wg,
                              const float* __restrict__ bg,
                              const float* __restrict__ Wn,
                              const float* __restrict__ bn) {
    extern __shared__ float Ws[];  // [16][DDIM], row o = output (0..7 Wg, 8..15 Wn)
    int tid = threadIdx.x;
    for (int idx = tid; idx < DDIM * NEXP; idx += blockDim.x) {
        int k = idx >> 3, o = idx & 7;
        Ws[o * DDIM + k]       = Wg[idx];
        Ws[(8 + o) * DDIM + k] = Wn[idx];
    }
    __syncthreads();
    int warp = tid >> 5, lane = tid & 31;
    for (int it = 0; it < 4; ++it) {
        int t = blockIdx.x * 32 + it * 8 + warp;
        float acc[16];
#pragma unroll
        for (int o = 0; o < 16; ++o) acc[o] = 0.f;
        const float* xr = x + (long)t * DDIM;
        for (int j = 0; j < 32; ++j) {
            int k = lane + 32 * j;
            float xv = xr[k];
#pragma unroll
            for (int o = 0; o < 16; ++o) acc[o] += xv * Ws[o * DDIM + k];
        }
#pragma unroll
        for (int o = 0; o < 16; ++o) {
            float v = acc[o];
            v += __shfl_xor_sync(0xffffffffu, v, 16);
            v += __shfl_xor_sync(0xffffffffu, v, 8);
            v += __shfl_xor_sync(0xffffffffu, v, 4);
            v += __shfl_xor_sync(0xffffffffu, v, 2);
            v += __shfl_xor_sync(0xffffffffu, v, 1);
            acc[o] = v;
        }
        if (lane == 0) {
            float noisy[8];
#pragma unroll
            for (int o = 0; o < 8; ++o) {
                float lg = acc[o] + bg[o];
                float nl = acc[8 + o] + bn[o];
                float sp = nl > 20.f ? nl : log1pf(expf(nl));
                noisy[o] = lg + noise[(long)t * 8 + o] * sp;
            }
            int i1 = 0; float v1 = noisy[0];
#pragma unroll
            for (int o = 1; o < 8; ++o) if (noisy[o] > v1) { v1 = noisy[o]; i1 = o; }
            int i2 = 0; float v2 = -3.4e38f;
#pragma unroll
            for (int o = 0; o < 8; ++o) if (o != i1 && noisy[o] > v2) { v2 = noisy[o]; i2 = o; }
            float ex = expf(v2 - v1);
            float inv = 1.f / (1.f + ex);
            float gg1 = inv, gg2 = ex * inv;
            int p1 = atomicAdd(&g_cnt[i1], 1);
            g_tok[i1 * NTOK + p1]  = t;
            g_gate[i1 * NTOK + p1] = gg1;
            int p2 = atomicAdd(&g_cnt[i2], 1);
            g_tok[i2 * NTOK + p2]  = t;
            g_gate[i2 * NTOK + p2] = gg2;
        }
    }
}

__global__ void scan_kernel() {
    if (threadIdx.x == 0) {
        int s = 0;
#pragma unroll
        for (int e = 0; e < NEXP; ++e) { g_off[e] = s; s += g_cnt[e]; }
    }
}

// ---------------- grouped GEMM (bf16x3 split, wmma) ----------------
// SECOND=false: h = relu(gather(x) @ W1[e] + b1[e])  -> g_hhi/g_hlo
// SECOND=true : out += gate * (h @ W2[e] + b2[e])     (atomicAdd, 2 adds/elem)
template <bool SECOND>
__global__ __launch_bounds__(256)
void moe_gemm_kernel(const float* __restrict__ bias, float* __restrict__ out) {
    const int KDIM = SECOND ? HDIM : DDIM;
    const int NW   = SECOND ? ODIM : HDIM;   // weight row stride
    int e  = blockIdx.y >> 5;
    int mt = blockIdx.y & 31;
    int cnt_e = g_cnt[e];
    int m0 = mt * BM;
    if (m0 >= cnt_e) return;
    int off_e = g_off[e];
    int n0 = blockIdx.x * BN;
    int tid = threadIdx.x;

    extern __shared__ __align__(128) char smem_raw[];
    __nv_bfloat16* sAhi = (__nv_bfloat16*)smem_raw;        // [2][BM][ALD]
    __nv_bfloat16* sAlo = sAhi + 2 * BM * ALD;
    __nv_bfloat16* sBhi = sAlo + 2 * BM * ALD;             // [2][BK][BLD]
    __nv_bfloat16* sBlo = sBhi + 2 * BK * BLD;
    float* sC = (float*)smem_raw;                          // [BM][CLD] (aliased)

    const __nv_bfloat16* Ahi = SECOND ? g_hhi : g_xhi;
    const __nv_bfloat16* Alo = SECOND ? g_hlo : g_xlo;
    const __nv_bfloat16* Bhi = SECOND ? g_w2hi : g_w1hi;
    const __nv_bfloat16* Blo = SECOND ? g_w2lo : g_w1lo;

    long abase[4]; bool aval[4]; long bbase[4];
#pragma unroll
    for (int v = 0; v < 4; ++v) {
        int idx = tid + 256 * v;
        int row = idx >> 3, cv = idx & 7;
        int pos = m0 + row;
        bool valid = pos < cnt_e;
        aval[v] = valid;
        if (SECOND) {
            abase[v] = valid ? ((long)(off_e + pos) * HDIM + cv * 4) : 0;
        } else {
            int token = valid ? g_tok[e * NTOK + pos] : 0;
            abase[v] = valid ? ((long)token * DDIM + cv * 4) : 0;
        }
        int brow = idx >> 5, cvb = idx & 31;
        bbase[v] = (long)e * KDIM * NW + (long)brow * NW + n0 + cvb * 4;
    }

    uint2 rAh[4], rAl[4], rBh[4], rBl[4];

    auto loadg = [&](int k0) {
#pragma unroll
        for (int v = 0; v < 4; ++v) {
            if (aval[v]) {
                rAh[v] = *(const uint2*)(Ahi + abase[v] + k0);
                rAl[v] = *(const uint2*)(Alo + abase[v] + k0);
            } else {
                rAh[v] = make_uint2(0u, 0u);
                rAl[v] = make_uint2(0u, 0u);
            }
            rBh[v] = *(const uint2*)(Bhi + bbase[v] + (long)k0 * NW);
            rBl[v] = *(const uint2*)(Blo + bbase[v] + (long)k0 * NW);
        }
    };
    auto stores = [&](int buf) {
#pragma unroll
        for (int v = 0; v < 4; ++v) {
            int idx = tid + 256 * v;
            int row = idx >> 3, cv = idx & 7;
            *(uint2*)(sAhi + buf * BM * ALD + row * ALD + cv * 4) = rAh[v];
            *(uint2*)(sAlo + buf * BM * ALD + row * ALD + cv * 4) = rAl[v];
            int brow = idx >> 5, cvb = idx & 31;
            *(uint2*)(sBhi + buf * BK * BLD + brow * BLD + cvb * 4) = rBh[v];
            *(uint2*)(sBlo + buf * BK * BLD + brow * BLD + cvb * 4) = rBl[v];
        }
    };

    int w = tid >> 5;
    int wm = (w & 3) * 32, wn = (w >> 2) * 64;

    wmma::fragment<wmma::accumulator, 16, 16, 16, float> acc[2][4];
#pragma unroll
    for (int i = 0; i < 2; ++i)
#pragma unroll
        for (int j = 0; j < 4; ++j) wmma::fill_fragment(acc[i][j], 0.f);

    auto compute = [&](int buf) {
#pragma unroll
        for (int kk = 0; kk < BK; kk += 16) {
            wmma::fragment<wmma::matrix_a, 16, 16, 16, __nv_bfloat16, wmma::row_major> fah[2], fal[2];
            wmma::fragment<wmma::matrix_b, 16, 16, 16, __nv_bfloat16, wmma::row_major> fbh[4], fbl[4];
#pragma unroll
            for (int i = 0; i < 2; ++i) {
                wmma::load_matrix_sync(fah[i], sAhi + buf * BM * ALD + (wm + 16 * i) * ALD + kk, ALD);
                wmma::load_matrix_sync(fal[i], sAlo + buf * BM * ALD + (wm + 16 * i) * ALD + kk, ALD);
            }
#pragma unroll
            for (int j = 0; j < 4; ++j) {
                wmma::load_matrix_sync(fbh[j], sBhi + buf * BK * BLD + kk * BLD + wn + 16 * j, BLD);
                wmma::load_matrix_sync(fbl[j], sBlo + buf * BK * BLD + kk * BLD + wn + 16 * j, BLD);
            }
#pragma unroll
            for (int i = 0; i < 2; ++i)
#pragma unroll
                for (int j = 0; j < 4; ++j) {
                    wmma::mma_sync(acc[i][j], fah[i], fbh[j], acc[i][j]);
                    wmma::mma_sync(acc[i][j], fah[i], fbl[j], acc[i][j]);
                    wmma::mma_sync(acc[i][j], fal[i], fbh[j], acc[i][j]);
                }
        }
    };

    const int KT = KDIM / BK;
    loadg(0);
    stores(0);
    __syncthreads();
#pragma unroll 1
    for (int kt = 0; kt < KT; ++kt) {
        if (kt + 1 < KT) loadg((kt + 1) * BK);
        compute(kt & 1);
        if (kt + 1 < KT) {
            stores((kt + 1) & 1);
            __syncthreads();
        }
    }

    __syncthreads();
#pragma unroll
    for (int i = 0; i < 2; ++i)
#pragma unroll
        for (int j = 0; j < 4; ++j)
            wmma::store_matrix_sync(sC + (wm + 16 * i) * CLD + wn + 16 * j, acc[i][j], CLD,
                                    wmma::mem_row_major);
    __syncthreads();

    for (int idx = tid; idx < BM * BN; idx += 256) {
        int r = idx >> 7, c = idx & 127;
        int pos = m0 + r;
        if (pos >= cnt_e) continue;
        float v = sC[r * CLD + c];
        if (!SECOND) {
            v += bias[e * HDIM + n0 + c];
            v = fmaxf(v, 0.f);
            __nv_bfloat16 hh = __float2bfloat16(v);
            long o = (long)(off_e + pos) * HDIM + n0 + c;
            g_hhi[o] = hh;
            g_hlo[o] = __float2bfloat16(v - __bfloat162float(hh));
        } else {
            v += bias[e * ODIM + n0 + c];
            v *= g_gate[e * NTOK + pos];
            int token = g_tok[e * NTOK + pos];
            atomicAdd(out + (long)token * ODIM + n0 + c, v);
        }
    }
}

// ---------------- launch ----------------
extern "C" void kernel_launch(void* const* d_in, const int* in_sizes, int n_in,
                              void* d_out, int out_size) {
    const float* x     = (const float*)d_in[0];
    const float* noise = (const float*)d_in[1];
    const float* Wg    = (const float*)d_in[2];
    const float* bg    = (const float*)d_in[3];
    const float* Wn    = (const float*)d_in[4];
    const float* bn    = (const float*)d_in[5];
    const float* W1    = (const float*)d_in[6];
    const float* b1    = (const float*)d_in[7];
    const float* W2    = (const float*)d_in[8];
    const float* b2    = (const float*)d_in[9];
    (void)in_sizes; (void)n_in;

    void *cnt_ptr, *xhi, *xlo, *w1hi, *w1lo, *w2hi, *w2lo;
    cudaGetSymbolAddress(&cnt_ptr, g_cnt);
    cudaGetSymbolAddress(&xhi,  g_xhi);
    cudaGetSymbolAddress(&xlo,  g_xlo);
    cudaGetSymbolAddress(&w1hi, g_w1hi);
    cudaGetSymbolAddress(&w1lo, g_w1lo);
    cudaGetSymbolAddress(&w2hi, g_w2hi);
    cudaGetSymbolAddress(&w2lo, g_w2lo);

    cudaFuncSetAttribute(router_kernel, cudaFuncAttributeMaxDynamicSharedMemorySize, SMEM_ROUTER);
    cudaFuncSetAttribute(moe_gemm_kernel<false>, cudaFuncAttributeMaxDynamicSharedMemorySize, SMEM_GEMM);
    cudaFuncSetAttribute(moe_gemm_kernel<true>,  cudaFuncAttributeMaxDynamicSharedMemorySize, SMEM_GEMM);

    cudaMemsetAsync(cnt_ptr, 0, NEXP * sizeof(int));
    cudaMemsetAsync(d_out, 0, (size_t)out_size * sizeof(float));

    int n4x = NTOK * DDIM / 4;
    split_kernel<<<(n4x + 255) / 256, 256>>>((const float4*)x, (__nv_bfloat162*)xhi,
                                             (__nv_bfloat162*)xlo, n4x);
    int n4w = NEXP * DDIM * HDIM / 4;
    split_kernel<<<(n4w + 255) / 256, 256>>>((const float4*)W1, (__nv_bfloat162*)w1hi,
                                             (__nv_bfloat162*)w1lo, n4w);
    split_kernel<<<(n4w + 255) / 256, 256>>>((const float4*)W2, (__nv_bfloat162*)w2hi,
                                             (__nv_bfloat162*)w2lo, n4w);

    router_kernel<<<NTOK / 32, 256, SMEM_ROUTER>>>(x, noise, Wg, bg, Wn, bn);
    scan_kernel<<<1, 32>>>();

    moe_gemm_kernel<false><<<dim3(HDIM / BN, NEXP * 32), 256, SMEM_GEMM>>>(b1, nullptr);
    moe_gemm_kernel<true> <<<dim3(ODIM / BN, NEXP * 32), 256, SMEM_GEMM>>>(b2, (float*)d_out);
}

// round 3
// speedup vs baseline: 1.4718x; 1.4718x over previous
#include <cuda_runtime.h>
#include <cuda_bf16.h>
#include <mma.h>
#include <math.h>
#include <cstdint>

using namespace nvcuda;

#define NTOK 4096
#define DDIM 1024
#define HDIM 4096
#define ODIM 1024
#define NEXP 8
#define NPAIR 8192

#define BM 128
#define BN 256
#define BK 64
#define ALD 72      // A smem row stride (elements)
#define BLD 264     // B smem row stride (elements)
#define CLD 264     // C smem row stride (floats)

// smem byte offsets
#define A_STAGE (BM * ALD * 2)          // 18432
#define B_STAGE (BK * BLD * 2)          // 33792
#define OFF_AHI 0
#define OFF_ALO (2 * A_STAGE)           // 36864
#define OFF_BHI (4 * A_STAGE)           // 73728
#define OFF_BLO (OFF_BHI + 2 * B_STAGE) // 141312
#define SMEM_GEMM (OFF_BLO + 2 * B_STAGE)  // 208896
#define SMEM_ROUTER (16 * DDIM * 4)

__device__ __forceinline__ uint32_t smem_u32(const void* p) {
    uint32_t a;
    asm("{ .reg .u64 t; cvta.to.shared.u64 t, %1; cvt.u32.u64 %0, t; }" : "=r"(a) : "l"(p));
    return a;
}
#define CP_ASYNC16(dst, src, sz) \
    asm volatile("cp.async.cg.shared.global [%0], [%1], 16, %2;" \
                 :: "r"(dst), "l"(src), "r"(sz))
#define CP_COMMIT() asm volatile("cp.async.commit_group;")
#define CP_WAIT0()  asm volatile("cp.async.wait_group 0;")

// ---------------- scratch (device globals) ----------------
__device__ int   g_cnt[NEXP];
__device__ int   g_off[NEXP];
__device__ int   g_tok[NEXP * NTOK];
__device__ float g_gate[NEXP * NTOK];
__device__ __nv_bfloat16 g_xhi[NTOK * DDIM];
__device__ __nv_bfloat16 g_xlo[NTOK * DDIM];
__device__ __nv_bfloat16 g_w1hi[NEXP * DDIM * HDIM];
__device__ __nv_bfloat16 g_w1lo[NEXP * DDIM * HDIM];
__device__ __nv_bfloat16 g_w2hi[NEXP * HDIM * ODIM];
__device__ __nv_bfloat16 g_w2lo[NEXP * HDIM * ODIM];
__device__ __nv_bfloat16 g_hhi[(size_t)NPAIR * HDIM];
__device__ __nv_bfloat16 g_hlo[(size_t)NPAIR * HDIM];

// ---------------- fp32 -> bf16 hi/lo split ----------------
__global__ void split_kernel(const float4* __restrict__ src,
                             __nv_bfloat162* __restrict__ hi,
                             __nv_bfloat162* __restrict__ lo, int n4) {
    int i = blockIdx.x * blockDim.x + threadIdx.x;
    if (i >= n4) return;
    float4 v = src[i];
    __nv_bfloat16 h0 = __float2bfloat16(v.x);
    __nv_bfloat16 h1 = __float2bfloat16(v.y);
    __nv_bfloat16 h2 = __float2bfloat16(v.z);
    __nv_bfloat16 h3 = __float2bfloat16(v.w);
    hi[2*i]   = __halves2bfloat162(h0, h1);
    hi[2*i+1] = __halves2bfloat162(h2, h3);
    lo[2*i]   = __halves2bfloat162(__float2bfloat16(v.x - __bfloat162float(h0)),
                                   __float2bfloat16(v.y - __bfloat162float(h1)));
    lo[2*i+1] = __halves2bfloat162(__float2bfloat16(v.z - __bfloat162float(h2)),
                                   __float2bfloat16(v.w - __bfloat162float(h3)));
}

// ---------------- router ----------------
__global__ void router_kernel(const float* __restrict__ x,
                              const float* __restrict__ noise,
                              const float* __restrict__ Wg,
                              const float* __restrict__ bg,
                              const float* __restrict__ Wn,
                              const float* __restrict__ bn) {
    extern __shared__ float Ws[];  // [16][DDIM]
    int tid = threadIdx.x;
    for (int idx = tid; idx < DDIM * NEXP; idx += blockDim.x) {
        int k = idx >> 3, o = idx & 7;
        Ws[o * DDIM + k]       = Wg[idx];
        Ws[(8 + o) * DDIM + k] = Wn[idx];
    }
    __syncthreads();
    int warp = tid >> 5, lane = tid & 31;
    int t = blockIdx.x * 8 + warp;
    float acc[16];
#pragma unroll
    for (int o = 0; o < 16; ++o) acc[o] = 0.f;
    const float* xr = x + (long)t * DDIM;
    for (int j = 0; j < 32; ++j) {
        int k = lane + 32 * j;
        float xv = xr[k];
#pragma unroll
        for (int o = 0; o < 16; ++o) acc[o] += xv * Ws[o * DDIM + k];
    }
#pragma unroll
    for (int o = 0; o < 16; ++o) {
        float v = acc[o];
        v += __shfl_xor_sync(0xffffffffu, v, 16);
        v += __shfl_xor_sync(0xffffffffu, v, 8);
        v += __shfl_xor_sync(0xffffffffu, v, 4);
        v += __shfl_xor_sync(0xffffffffu, v, 2);
        v += __shfl_xor_sync(0xffffffffu, v, 1);
        acc[o] = v;
    }
    if (lane == 0) {
        float noisy[8];
#pragma unroll
        for (int o = 0; o < 8; ++o) {
            float lg = acc[o] + bg[o];
            float nl = acc[8 + o] + bn[o];
            float sp = nl > 20.f ? nl : log1pf(expf(nl));
            noisy[o] = lg + noise[(long)t * 8 + o] * sp;
        }
        int i1 = 0; float v1 = noisy[0];
#pragma unroll
        for (int o = 1; o < 8; ++o) if (noisy[o] > v1) { v1 = noisy[o]; i1 = o; }
        int i2 = 0; float v2 = -3.4e38f;
#pragma unroll
        for (int o = 0; o < 8; ++o) if (o != i1 && noisy[o] > v2) { v2 = noisy[o]; i2 = o; }
        float ex = expf(v2 - v1);
        float inv = 1.f / (1.f + ex);
        int p1 = atomicAdd(&g_cnt[i1], 1);
        g_tok[i1 * NTOK + p1]  = t;
        g_gate[i1 * NTOK + p1] = inv;
        int p2 = atomicAdd(&g_cnt[i2], 1);
        g_tok[i2 * NTOK + p2]  = t;
        g_gate[i2 * NTOK + p2] = ex * inv;
    }
}

__global__ void scan_kernel() {
    if (threadIdx.x == 0) {
        int s = 0;
#pragma unroll
        for (int e = 0; e < NEXP; ++e) { g_off[e] = s; s += g_cnt[e]; }
    }
}

// ---------------- grouped GEMM (bf16x3, wmma, cp.async pipeline) ----------------
// SECOND=false: h = relu(gather(xhi/xlo) @ W1[e] + b1[e]) -> g_hhi/g_hlo
// SECOND=true : out += gate * (h @ W2[e] + b2[e])
template <bool SECOND>
__global__ void __launch_bounds__(256, 1)
moe_gemm_kernel(const float* __restrict__ bias, float* __restrict__ out) {
    constexpr int KDIM = SECOND ? HDIM : DDIM;
    constexpr int NDIM = SECOND ? ODIM : HDIM;
    constexpr int KT = KDIM / BK;

    int e  = blockIdx.y >> 5;
    int mt = blockIdx.y & 31;
    int cnt = g_cnt[e];
    int m0 = mt * BM;
    if (m0 >= cnt) return;
    int off = g_off[e];
    int n0 = blockIdx.x * BN;
    int tid = threadIdx.x;
    int w = tid >> 5;
    int wm = (w & 1) * 64, wn = (w >> 1) * 64;

    extern __shared__ __align__(128) char raw[];
    uint32_t sbase = smem_u32(raw);

    const __nv_bfloat16* Ahi = SECOND ? g_hhi : g_xhi;
    const __nv_bfloat16* Alo = SECOND ? g_hlo : g_xlo;
    const __nv_bfloat16* Bhi = SECOND ? g_w2hi : g_w1hi;
    const __nv_bfloat16* Blo = SECOND ? g_w2lo : g_w1lo;

    // A mapping: chunk id = tid + 256*i (i<4): row = id>>3, c8 = id&7 (8 elems)
    size_t asrc[4]; uint32_t asz[4]; uint32_t adst[4];
#pragma unroll
    for (int i = 0; i < 4; ++i) {
        int id = tid + 256 * i;
        int row = id >> 3, c8 = id & 7;
        int pos = m0 + row;
        bool aval = pos < cnt;
        asz[i] = aval ? 16u : 0u;
        if (SECOND) {
            asrc[i] = (size_t)(off + (aval ? pos : 0)) * HDIM + c8 * 8;
        } else {
            int token = aval ? g_tok[e * NTOK + pos] : 0;
            asrc[i] = (size_t)token * DDIM + c8 * 8;
        }
        adst[i] = sbase + row * (ALD * 2) + c8 * 16;
    }
    // B mapping: chunk id = tid + 256*i (i<8): row = id>>5, c16 = id&31
    size_t bsrc[8]; uint32_t bdst[8];
#pragma unroll
    for (int i = 0; i < 8; ++i) {
        int id = tid + 256 * i;
        int row = id >> 5, c16 = id & 31;
        bsrc[i] = (size_t)e * KDIM * NDIM + (size_t)row * NDIM + n0 + c16 * 8;
        bdst[i] = sbase + OFF_BHI + row * (BLD * 2) + c16 * 16;
    }

    auto fill = [&](int s, int kt) {
        int ko = kt * BK;
        uint32_t sa = s * A_STAGE, sb = s * B_STAGE;
#pragma unroll
        for (int i = 0; i < 4; ++i) {
            CP_ASYNC16(adst[i] + sa, (const char*)(Ahi + asrc[i] + ko), asz[i]);
            CP_ASYNC16(adst[i] + sa + OFF_ALO, (const char*)(Alo + asrc[i] + ko), asz[i]);
        }
        size_t kofs = (size_t)ko * NDIM;
#pragma unroll
        for (int i = 0; i < 8; ++i) {
            CP_ASYNC16(bdst[i] + sb, (const char*)(Bhi + bsrc[i] + kofs), 16u);
            CP_ASYNC16(bdst[i] + sb + (OFF_BLO - OFF_BHI), (const char*)(Blo + bsrc[i] + kofs), 16u);
        }
        CP_COMMIT();
    };

    wmma::fragment<wmma::accumulator, 16, 16, 16, float> acc[4][4];
#pragma unroll
    for (int i = 0; i < 4; ++i)
#pragma unroll
        for (int j = 0; j < 4; ++j) wmma::fill_fragment(acc[i][j], 0.f);

    auto compute = [&](int s) {
        const __nv_bfloat16* Ah = (const __nv_bfloat16*)(raw + s * A_STAGE);
        const __nv_bfloat16* Al = (const __nv_bfloat16*)(raw + OFF_ALO + s * A_STAGE);
        const __nv_bfloat16* Bh = (const __nv_bfloat16*)(raw + OFF_BHI + s * B_STAGE);
        const __nv_bfloat16* Bl = (const __nv_bfloat16*)(raw + OFF_BLO + s * B_STAGE);
#pragma unroll
        for (int kk = 0; kk < BK; kk += 16) {
            wmma::fragment<wmma::matrix_a, 16, 16, 16, __nv_bfloat16, wmma::row_major> fa[4];
            wmma::fragment<wmma::matrix_b, 16, 16, 16, __nv_bfloat16, wmma::row_major> fbh[4], fbl[4];
#pragma unroll
            for (int i = 0; i < 4; ++i)
                wmma::load_matrix_sync(fa[i], Ah + (wm + 16 * i) * ALD + kk, ALD);
#pragma unroll
            for (int j = 0; j < 4; ++j) {
                wmma::load_matrix_sync(fbh[j], Bh + kk * BLD + wn + 16 * j, BLD);
                wmma::load_matrix_sync(fbl[j], Bl + kk * BLD + wn + 16 * j, BLD);
            }
#pragma unroll
            for (int i = 0; i < 4; ++i)
#pragma unroll
                for (int j = 0; j < 4; ++j) {
                    wmma::mma_sync(acc[i][j], fa[i], fbh[j], acc[i][j]);
                    wmma::mma_sync(acc[i][j], fa[i], fbl[j], acc[i][j]);
                }
#pragma unroll
            for (int i = 0; i < 4; ++i)
                wmma::load_matrix_sync(fa[i], Al + (wm + 16 * i) * ALD + kk, ALD);
#pragma unroll
            for (int i = 0; i < 4; ++i)
#pragma unroll
                for (int j = 0; j < 4; ++j)
                    wmma::mma_sync(acc[i][j], fa[i], fbh[j], acc[i][j]);
        }
    };

    fill(0, 0);
    CP_WAIT0();
    __syncthreads();
#pragma unroll 1
    for (int kt = 0; kt < KT; ++kt) {
        int s = kt & 1;
        if (kt + 1 < KT) fill(s ^ 1, kt + 1);
        compute(s);
        if (kt + 1 < KT) {
            CP_WAIT0();
            __syncthreads();
        }
    }

    // epilogue via smem C tile (aliased over stage buffers)
    __syncthreads();
    float* sC = (float*)raw;
#pragma unroll
    for (int i = 0; i < 4; ++i)
#pragma unroll
        for (int j = 0; j < 4; ++j)
            wmma::store_matrix_sync(sC + (wm + 16 * i) * CLD + wn + 16 * j, acc[i][j], CLD,
                                    wmma::mem_row_major);
    __syncthreads();

    for (int q = tid; q < BM * (BN / 4); q += 256) {
        int r = q >> 6;
        int c = (q & 63) * 4;
        int pos = m0 + r;
        if (pos >= cnt) continue;
        int nb = n0 + c;
        float v0 = sC[r * CLD + c]     + bias[e * NDIM + nb];
        float v1 = sC[r * CLD + c + 1] + bias[e * NDIM + nb + 1];
        float v2 = sC[r * CLD + c + 2] + bias[e * NDIM + nb + 2];
        float v3 = sC[r * CLD + c + 3] + bias[e * NDIM + nb + 3];
        if (!SECOND) {
            v0 = fmaxf(v0, 0.f); v1 = fmaxf(v1, 0.f);
            v2 = fmaxf(v2, 0.f); v3 = fmaxf(v3, 0.f);
            __nv_bfloat16 h0 = __float2bfloat16(v0), h1 = __float2bfloat16(v1);
            __nv_bfloat16 h2 = __float2bfloat16(v2), h3 = __float2bfloat16(v3);
            __nv_bfloat162 phA = __halves2bfloat162(h0, h1);
            __nv_bfloat162 phB = __halves2bfloat162(h2, h3);
            __nv_bfloat162 plA = __halves2bfloat162(__float2bfloat16(v0 - __bfloat162float(h0)),
                                                    __float2bfloat16(v1 - __bfloat162float(h1)));
            __nv_bfloat162 plB = __halves2bfloat162(__float2bfloat16(v2 - __bfloat162float(h2)),
                                                    __float2bfloat16(v3 - __bfloat162float(h3)));
            size_t ob = (size_t)(off + pos) * HDIM + nb;
            uint2 hh, ll;
            hh.x = *(uint32_t*)&phA; hh.y = *(uint32_t*)&phB;
            ll.x = *(uint32_t*)&plA; ll.y = *(uint32_t*)&plB;
            *(uint2*)(g_hhi + ob) = hh;
            *(uint2*)(g_hlo + ob) = ll;
        } else {
            float gate = g_gate[e * NTOK + pos];
            int token  = g_tok[e * NTOK + pos];
            float* op = out + (size_t)token * ODIM + nb;
            atomicAdd(op,     v0 * gate);
            atomicAdd(op + 1, v1 * gate);
            atomicAdd(op + 2, v2 * gate);
            atomicAdd(op + 3, v3 * gate);
        }
    }
}

// ---------------- launch ----------------
extern "C" void kernel_launch(void* const* d_in, const int* in_sizes, int n_in,
                              void* d_out, int out_size) {
    const float* x     = (const float*)d_in[0];
    const float* noise = (const float*)d_in[1];
    const float* Wg    = (const float*)d_in[2];
    const float* bg    = (const float*)d_in[3];
    const float* Wn    = (const float*)d_in[4];
    const float* bn    = (const float*)d_in[5];
    const float* W1    = (const float*)d_in[6];
    const float* b1    = (const float*)d_in[7];
    const float* W2    = (const float*)d_in[8];
    const float* b2    = (const float*)d_in[9];
    (void)in_sizes; (void)n_in;

    void *cnt_ptr, *xhi, *xlo, *w1hi, *w1lo, *w2hi, *w2lo;
    cudaGetSymbolAddress(&cnt_ptr, g_cnt);
    cudaGetSymbolAddress(&xhi,  g_xhi);
    cudaGetSymbolAddress(&xlo,  g_xlo);
    cudaGetSymbolAddress(&w1hi, g_w1hi);
    cudaGetSymbolAddress(&w1lo, g_w1lo);
    cudaGetSymbolAddress(&w2hi, g_w2hi);
    cudaGetSymbolAddress(&w2lo, g_w2lo);

    cudaFuncSetAttribute(router_kernel, cudaFuncAttributeMaxDynamicSharedMemorySize, SMEM_ROUTER);
    cudaFuncSetAttribute(moe_gemm_kernel<false>, cudaFuncAttributeMaxDynamicSharedMemorySize, SMEM_GEMM);
    cudaFuncSetAttribute(moe_gemm_kernel<true>,  cudaFuncAttributeMaxDynamicSharedMemorySize, SMEM_GEMM);

    cudaMemsetAsync(cnt_ptr, 0, NEXP * sizeof(int));
    cudaMemsetAsync(d_out, 0, (size_t)out_size * sizeof(float));

    int n4x = NTOK * DDIM / 4;
    split_kernel<<<(n4x + 255) / 256, 256>>>((const float4*)x, (__nv_bfloat162*)xhi,
                                             (__nv_bfloat162*)xlo, n4x);
    int n4w = NEXP * DDIM * HDIM / 4;
    split_kernel<<<(n4w + 255) / 256, 256>>>((const float4*)W1, (__nv_bfloat162*)w1hi,
                                             (__nv_bfloat162*)w1lo, n4w);
    split_kernel<<<(n4w + 255) / 256, 256>>>((const float4*)W2, (__nv_bfloat162*)w2hi,
                                             (__nv_bfloat162*)w2lo, n4w);

    router_kernel<<<NTOK / 8, 256, SMEM_ROUTER>>>(x, noise, Wg, bg, Wn, bn);
    scan_kernel<<<1, 32>>>();

    moe_gemm_kernel<false><<<dim3(HDIM / BN, NEXP * 32), 256, SMEM_GEMM>>>(b1, nullptr);
    moe_gemm_kernel<true> <<<dim3(ODIM / BN, NEXP * 32), 256, SMEM_GEMM>>>(b2, (float*)d_out);
}